// round 1
// baseline (speedup 1.0000x reference)
#include <cuda_runtime.h>
#include <math.h>

#define Dm    128
#define NMAX  50000
#define EMAX  800000

// ---- scratch (static device allocation; no cudaMalloc allowed) ----
static __device__ float g_Ah[NMAX * Dm];
static __device__ float g_Bh[NMAX * Dm];
static __device__ float g_Dh[NMAX * Dm];
static __device__ float g_Eh[NMAX * Dm];
static __device__ float g_ssh[NMAX * Dm];           // sum_sigma_h accumulator
static __device__ float g_enew[(size_t)EMAX * Dm];  // e_new (pre-BN)
static __device__ float g_hsum[Dm], g_hsq[Dm], g_esum[Dm], g_esq[Dm];

#define SMEM_BYTES ((128 * 129 + 64 * 128) * 4)

// ---------------------------------------------------------------------------
// zero scratch accumulators (graph-replay safe: every launch re-zeros)
// ---------------------------------------------------------------------------
__global__ void k_zero() {
    int i = blockIdx.x * blockDim.x + threadIdx.x;
    int stride = gridDim.x * blockDim.x;
    for (int j = i; j < NMAX * Dm; j += stride) g_ssh[j] = 0.f;
    if (i < Dm) { g_hsum[i] = 0.f; g_hsq[i] = 0.f; g_esum[i] = 0.f; g_esq[i] = 0.f; }
}

// ---------------------------------------------------------------------------
// Node GEMM: out = h @ W.T + b for the 4 node weights (blockIdx.y selects).
// Tile: 64 rows x 128 cols, K=128. 256 threads, 8x4 register microtile.
// W in smem as ws[c][k] with pad 129 -> conflict-free strided-col reads.
// ---------------------------------------------------------------------------
__global__ void k_node_gemm(const float* __restrict__ h, int Nn,
                            const float* __restrict__ WA, const float* __restrict__ bA,
                            const float* __restrict__ WB, const float* __restrict__ bB,
                            const float* __restrict__ WD, const float* __restrict__ bD,
                            const float* __restrict__ WE, const float* __restrict__ bE) {
    extern __shared__ float sm[];
    float* ws = sm;             // [128][129]
    float* hs = sm + 128 * 129; // [64][128]

    const float* Wp; const float* bp; float* outp;
    switch (blockIdx.y) {
        case 0:  Wp = WA; bp = bA; outp = g_Ah; break;
        case 1:  Wp = WB; bp = bB; outp = g_Bh; break;
        case 2:  Wp = WD; bp = bD; outp = g_Dh; break;
        default: Wp = WE; bp = bE; outp = g_Eh; break;
    }

    int tid = threadIdx.x;
    for (int idx = tid; idx < 128 * 128; idx += 256) {
        int c = idx >> 7, k = idx & 127;
        ws[c * 129 + k] = Wp[idx];
    }
    int row0 = blockIdx.x * 64;
    for (int idx = tid; idx < 64 * 128; idx += 256) {
        int r = row0 + (idx >> 7);
        hs[idx] = (r < Nn) ? h[r * Dm + (idx & 127)] : 0.f;
    }
    __syncthreads();

    int w = tid >> 5, l = tid & 31;
    float acc[8][4];
#pragma unroll
    for (int i = 0; i < 4; i++) {
        float bb = bp[l + 32 * i];
#pragma unroll
        for (int j = 0; j < 8; j++) acc[j][i] = bb;
    }

    const float* hrow = hs + (w * 8) * 128;
#pragma unroll 4
    for (int k = 0; k < 128; k++) {
        float bw[4];
#pragma unroll
        for (int i = 0; i < 4; i++) bw[i] = ws[(l + 32 * i) * 129 + k];
#pragma unroll
        for (int j = 0; j < 8; j++) {
            float a = hrow[j * 128 + k];
#pragma unroll
            for (int i = 0; i < 4; i++) acc[j][i] += a * bw[i];
        }
    }

#pragma unroll
    for (int j = 0; j < 8; j++) {
        int r = row0 + w * 8 + j;
        if (r < Nn) {
#pragma unroll
            for (int i = 0; i < 4; i++) outp[r * Dm + l + 32 * i] = acc[j][i];
        }
    }
}

// ---------------------------------------------------------------------------
// Fused edge kernel: Ce GEMM tile (64 edges) + full edge epilogue:
//   DEh = Dh[dst]-Eh[src]; he = Bh[src]+DEh; e_new = DEh+Ce
//   sigma = exp(-0.5*||e_new||); directional gate; scatter he*gate to dst
//   + per-column BN stats of e_new
// ---------------------------------------------------------------------------
__global__ void k_edge(const float* __restrict__ e,
                       const int* __restrict__ src, const int* __restrict__ dst,
                       const int* __restrict__ smask,
                       const float* __restrict__ diff, const float* __restrict__ dist,
                       const float* __restrict__ dirn,
                       const float* __restrict__ WC, const float* __restrict__ bC,
                       int Ee) {
    extern __shared__ float sm[];
    float* ws = sm;             // [128][129]
    float* es = sm + 128 * 129; // [64][128]
    __shared__ float s_sum[128], s_sq[128];

    int tid = threadIdx.x;
    if (tid < 128) { s_sum[tid] = 0.f; s_sq[tid] = 0.f; }

    for (int idx = tid; idx < 128 * 128; idx += 256) {
        int c = idx >> 7, k = idx & 127;
        ws[c * 129 + k] = WC[idx];
    }
    int row0 = blockIdx.x * 64;
    for (int idx = tid; idx < 64 * 128; idx += 256) {
        int m = row0 + (idx >> 7);
        es[idx] = (m < Ee) ? e[m * Dm + (idx & 127)] : 0.f;
    }
    __syncthreads();

    int w = tid >> 5, l = tid & 31;
    float acc[8][4];
#pragma unroll
    for (int i = 0; i < 4; i++) {
        float bb = bC[l + 32 * i];
#pragma unroll
        for (int j = 0; j < 8; j++) acc[j][i] = bb;
    }

    const float* erow = es + (w * 8) * 128;
#pragma unroll 4
    for (int k = 0; k < 128; k++) {
        float bw[4];
#pragma unroll
        for (int i = 0; i < 4; i++) bw[i] = ws[(l + 32 * i) * 129 + k];
#pragma unroll
        for (int j = 0; j < 8; j++) {
            float a = erow[j * 128 + k];
#pragma unroll
            for (int i = 0; i < 4; i++) acc[j][i] += a * bw[i];
        }
    }

    float psum[4] = {0.f, 0.f, 0.f, 0.f};
    float psq[4]  = {0.f, 0.f, 0.f, 0.f};

#pragma unroll 1
    for (int j = 0; j < 8; j++) {
        int m = row0 + w * 8 + j;
        if (m < Ee) {
            int s = src[m], t = dst[m];
            float hev[4];
            float nrm = 0.f;
#pragma unroll
            for (int i = 0; i < 4; i++) {
                int c = l + 32 * i;
                float de  = g_Dh[t * Dm + c] - g_Eh[s * Dm + c];
                float env = de + acc[j][i];                  // e_new = DEh + Ce
                hev[i] = g_Bh[s * Dm + c] + de;              // he = Bh[src] + DEh
                g_enew[(size_t)m * Dm + c] = env;
                nrm     += env * env;
                psum[i] += env;
                psq[i]  += env * env;
            }
#pragma unroll
            for (int o = 16; o > 0; o >>= 1)
                nrm += __shfl_xor_sync(0xffffffffu, nrm, o);
            float sigma = expf(-0.5f * sqrtf(nrm));

            float dd  = dist[m];
            float f0  = diff[2 * m], f1 = diff[2 * m + 1];
            float inv = (dd > 0.f) ? (1.f / dd) : 1.f;
            float ed0 = f0 * inv, ed1 = f1 * inv;
            float vs0 = dirn[2 * s], vs1 = dirn[2 * s + 1];
            float vd0 = dirn[2 * t], vd1 = dirn[2 * t + 1];
            float uv  = vs0 * vd0 + vs1 * vd1;
            float ehd = ed0 * vd0 + ed1 * vd1;
            float gate = (smask[m] == 1) ? (0.5f * (1.f - ehd) * uv * sigma) : sigma;

#pragma unroll
            for (int i = 0; i < 4; i++)
                atomicAdd(&g_ssh[t * Dm + l + 32 * i], hev[i] * gate);
        }
    }

#pragma unroll
    for (int i = 0; i < 4; i++) {
        atomicAdd(&s_sum[l + 32 * i], psum[i]);
        atomicAdd(&s_sq[l + 32 * i],  psq[i]);
    }
    __syncthreads();
    if (tid < 128) {
        atomicAdd(&g_esum[tid], s_sum[tid]);
        atomicAdd(&g_esq[tid],  s_sq[tid]);
    }
}

// ---------------------------------------------------------------------------
// BN stats for h_out_pre = Ah + sum_sigma_h
// ---------------------------------------------------------------------------
__global__ void k_hstats(int Nn) {
    __shared__ float ss[2][128], sq[2][128];
    int c  = threadIdx.x & 127;
    int rg = threadIdx.x >> 7;
    int r0 = blockIdx.x * 64;
    float s = 0.f, q = 0.f;
    for (int r = r0 + rg; r < r0 + 64 && r < Nn; r += 2) {
        float x = g_Ah[r * Dm + c] + g_ssh[r * Dm + c];
        s += x; q += x * x;
    }
    ss[rg][c] = s; sq[rg][c] = q;
    __syncthreads();
    if (rg == 0) {
        atomicAdd(&g_hsum[c], ss[0][c] + ss[1][c]);
        atomicAdd(&g_hsq[c],  sq[0][c] + sq[1][c]);
    }
}

// ---------------------------------------------------------------------------
// h epilogue: h_out = h + relu(BN(Ah + ssh))
// ---------------------------------------------------------------------------
__global__ void k_hout(const float* __restrict__ h,
                       const float* __restrict__ gamma, const float* __restrict__ beta,
                       float* __restrict__ out, int Nn) {
    int idx = blockIdx.x * blockDim.x + threadIdx.x;
    if (idx >= Nn * Dm) return;
    int c = idx & 127;
    float invN = 1.f / (float)Nn;
    float mu  = g_hsum[c] * invN;
    float var = fmaxf(g_hsq[c] * invN - mu * mu, 0.f);
    float x = g_Ah[idx] + g_ssh[idx];
    float y = gamma[c] * (x - mu) * rsqrtf(var + 1e-5f) + beta[c];
    out[idx] = h[idx] + fmaxf(y, 0.f);
}

// ---------------------------------------------------------------------------
// e epilogue: e_out = e + relu(BN(e_new))
// ---------------------------------------------------------------------------
__global__ void k_eout(const float* __restrict__ e,
                       const float* __restrict__ gamma, const float* __restrict__ beta,
                       float* __restrict__ out, int Ee) {
    int idx = blockIdx.x * blockDim.x + threadIdx.x;
    if (idx >= Ee * Dm) return;
    int c = idx & 127;
    float invE = 1.f / (float)Ee;
    float mu  = g_esum[c] * invE;
    float var = fmaxf(g_esq[c] * invE - mu * mu, 0.f);
    float x = g_enew[idx];
    float y = gamma[c] * (x - mu) * rsqrtf(var + 1e-5f) + beta[c];
    out[idx] = e[idx] + fmaxf(y, 0.f);
}

// ---------------------------------------------------------------------------
extern "C" void kernel_launch(void* const* d_in, const int* in_sizes, int n_in,
                              void* d_out, int out_size) {
    const float* h     = (const float*)d_in[0];
    const float* e     = (const float*)d_in[1];
    const int*   src   = (const int*)d_in[2];
    const int*   dst   = (const int*)d_in[3];
    const int*   smask = (const int*)d_in[4];
    const float* diff  = (const float*)d_in[5];
    const float* dist  = (const float*)d_in[6];
    const float* dirn  = (const float*)d_in[7];
    const float* WA = (const float*)d_in[8],  *bA = (const float*)d_in[9];
    const float* WB = (const float*)d_in[10], *bB = (const float*)d_in[11];
    const float* WC = (const float*)d_in[12], *bC = (const float*)d_in[13];
    const float* WD = (const float*)d_in[14], *bD = (const float*)d_in[15];
    const float* WE = (const float*)d_in[16], *bE = (const float*)d_in[17];
    const float* gh = (const float*)d_in[18], *bh = (const float*)d_in[19];
    const float* ge = (const float*)d_in[20], *be = (const float*)d_in[21];
    float* out = (float*)d_out;

    int Nn = in_sizes[0] / Dm;
    int Ee = in_sizes[2];

    cudaFuncSetAttribute(k_node_gemm, cudaFuncAttributeMaxDynamicSharedMemorySize, SMEM_BYTES);
    cudaFuncSetAttribute(k_edge,      cudaFuncAttributeMaxDynamicSharedMemorySize, SMEM_BYTES);

    k_zero<<<256, 256>>>();

    dim3 g1((Nn + 63) / 64, 4);
    k_node_gemm<<<g1, 256, SMEM_BYTES>>>(h, Nn, WA, bA, WB, bB, WD, bD, WE, bE);

    k_edge<<<(Ee + 63) / 64, 256, SMEM_BYTES>>>(e, src, dst, smask, diff, dist, dirn, WC, bC, Ee);

    k_hstats<<<(Nn + 63) / 64, 256>>>(Nn);

    k_hout<<<(Nn * Dm + 255) / 256, 256>>>(h, gh, bh, out, Nn);

    k_eout<<<(Ee * Dm + 255) / 256, 256>>>(e, ge, be, out + (size_t)Nn * Dm, Ee);
}

// round 2
// speedup vs baseline: 1.2751x; 1.2751x over previous
#include <cuda_runtime.h>
#include <math.h>

#define Dm    128
#define NMAX  50000
#define EMAX  800000

#define WS 136   // wsT smem stride (uints): banks 8a+b -> conflict-free B frags
#define ES 132   // A-tile smem stride: banks 4b+a -> conflict-free A frags
#define SMEM_GEMM ((128 * WS + 128 * ES) * 4)

// ---- scratch (static device allocation; no cudaMalloc allowed) ----
static __device__ float g_Ah[NMAX * Dm];
static __device__ float g_Bh[NMAX * Dm];
static __device__ float g_Dh[NMAX * Dm];
static __device__ float g_Eh[NMAX * Dm];
static __device__ float g_ssh[NMAX * Dm];           // sum_sigma_h accumulator
static __device__ float g_enew[(size_t)EMAX * Dm];  // e_new (pre-BN)
static __device__ float g_hsum[Dm], g_hsq[Dm], g_esum[Dm], g_esq[Dm];

// ---------------------------------------------------------------------------
__device__ __forceinline__ unsigned f2tf(float x) {
    unsigned r;
    asm("cvt.rna.tf32.f32 %0, %1;" : "=r"(r) : "f"(x));
    return r;
}

__device__ __forceinline__ void mma_tf32(float* c,
                                         unsigned a0, unsigned a1, unsigned a2, unsigned a3,
                                         unsigned b0, unsigned b1) {
    asm volatile(
        "mma.sync.aligned.m16n8k8.row.col.f32.tf32.tf32.f32 "
        "{%0,%1,%2,%3}, {%4,%5,%6,%7}, {%8,%9}, {%0,%1,%2,%3};"
        : "+f"(c[0]), "+f"(c[1]), "+f"(c[2]), "+f"(c[3])
        : "r"(a0), "r"(a1), "r"(a2), "r"(a3), "r"(b0), "r"(b1));
}

__device__ __forceinline__ void red_add_v4(float* p, float x, float y, float z, float w) {
    asm volatile("red.global.add.v4.f32 [%0], {%1,%2,%3,%4};"
                 :: "l"(p), "f"(x), "f"(y), "f"(z), "f"(w) : "memory");
}

// ---------------------------------------------------------------------------
// zero scratch accumulators (graph-replay safe)
// ---------------------------------------------------------------------------
__global__ void k_zero() {
    int i = blockIdx.x * blockDim.x + threadIdx.x;
    int stride = gridDim.x * blockDim.x;
    float4 z = make_float4(0.f, 0.f, 0.f, 0.f);
    for (int j = i; j < NMAX * Dm / 4; j += stride)
        ((float4*)g_ssh)[j] = z;
    if (i < Dm) { g_hsum[i] = 0.f; g_hsq[i] = 0.f; g_esum[i] = 0.f; g_esq[i] = 0.f; }
}

// ---------------------------------------------------------------------------
// Node GEMM via tf32 mma: out = h @ W.T + b, blockIdx.y selects weight.
// Block tile 128x128, K=128. 8 warps as 4(m) x 2(n); warp tile 32m x 64n.
// ---------------------------------------------------------------------------
__global__ void k_node_gemm(const float* __restrict__ h, int Nn,
                            const float* __restrict__ WA, const float* __restrict__ bA,
                            const float* __restrict__ WB, const float* __restrict__ bB,
                            const float* __restrict__ WD, const float* __restrict__ bD,
                            const float* __restrict__ WE, const float* __restrict__ bE) {
    extern __shared__ unsigned smu[];
    unsigned* wsT = smu;             // [128][WS]  wsT[k][n] = tf32(W[n][k])
    unsigned* es  = smu + 128 * WS;  // [128][ES]  tf32 A tile

    const float* Wp; const float* bp; float* outp;
    switch (blockIdx.y) {
        case 0:  Wp = WA; bp = bA; outp = g_Ah; break;
        case 1:  Wp = WB; bp = bB; outp = g_Bh; break;
        case 2:  Wp = WD; bp = bD; outp = g_Dh; break;
        default: Wp = WE; bp = bE; outp = g_Eh; break;
    }

    int tid = threadIdx.x;
    for (int idx = tid; idx < 128 * 128; idx += 256) {
        int n = idx >> 7, k = idx & 127;
        wsT[k * WS + n] = f2tf(Wp[idx]);
    }
    int row0 = blockIdx.x * 128;
    for (int idx = tid; idx < 128 * 32; idx += 256) {
        int r = idx >> 5, c4 = (idx & 31) * 4;
        float4 v = (row0 + r < Nn) ? *(const float4*)(h + (size_t)(row0 + r) * Dm + c4)
                                   : make_float4(0.f, 0.f, 0.f, 0.f);
        uint4 u = { f2tf(v.x), f2tf(v.y), f2tf(v.z), f2tf(v.w) };
        *(uint4*)(es + r * ES + c4) = u;
    }
    __syncthreads();

    int wa = tid >> 5, lane = tid & 31;
    int wm = wa >> 1, wn = wa & 1;
    int q = lane >> 2, a = lane & 3;

    float acc[2][8][4];
#pragma unroll
    for (int mf = 0; mf < 2; mf++)
#pragma unroll
        for (int nf = 0; nf < 8; nf++)
#pragma unroll
            for (int i = 0; i < 4; i++) acc[mf][nf][i] = 0.f;

#pragma unroll
    for (int k0 = 0; k0 < 128; k0 += 8) {
        unsigned A[2][4];
#pragma unroll
        for (int mf = 0; mf < 2; mf++) {
            int r = wm * 32 + mf * 16 + q;
            A[mf][0] = es[r * ES + k0 + a];
            A[mf][1] = es[(r + 8) * ES + k0 + a];
            A[mf][2] = es[r * ES + k0 + a + 4];
            A[mf][3] = es[(r + 8) * ES + k0 + a + 4];
        }
        unsigned B[8][2];
#pragma unroll
        for (int nf = 0; nf < 8; nf++) {
            int n = wn * 64 + nf * 8 + q;
            B[nf][0] = wsT[(k0 + a) * WS + n];
            B[nf][1] = wsT[(k0 + a + 4) * WS + n];
        }
#pragma unroll
        for (int mf = 0; mf < 2; mf++)
#pragma unroll
            for (int nf = 0; nf < 8; nf++)
                mma_tf32(acc[mf][nf], A[mf][0], A[mf][1], A[mf][2], A[mf][3],
                         B[nf][0], B[nf][1]);
    }

    // store with bias (STG.64)
#pragma unroll
    for (int mf = 0; mf < 2; mf++)
#pragma unroll
        for (int nf = 0; nf < 8; nf++) {
            int col = wn * 64 + nf * 8 + 2 * a;
            float b0 = bp[col], b1 = bp[col + 1];
            int r0 = row0 + wm * 32 + mf * 16 + q;
            if (r0 < Nn) {
                float2 v = { acc[mf][nf][0] + b0, acc[mf][nf][1] + b1 };
                *(float2*)(outp + (size_t)r0 * Dm + col) = v;
            }
            if (r0 + 8 < Nn) {
                float2 v = { acc[mf][nf][2] + b0, acc[mf][nf][3] + b1 };
                *(float2*)(outp + (size_t)(r0 + 8) * Dm + col) = v;
            }
        }
}

// ---------------------------------------------------------------------------
// Fused edge kernel: Ce tf32 GEMM (128 edges/block) + epilogue:
//   DEh = Dh[dst]-Eh[src]; he = Bh[src]+DEh; e_new = DEh+Ce
//   sigma = exp(-0.5*||e_new||); directional gate; red.v4 scatter; e-BN stats
// ---------------------------------------------------------------------------
__global__ void k_edge(const float* __restrict__ e,
                       const int* __restrict__ src, const int* __restrict__ dst,
                       const int* __restrict__ smask,
                       const float* __restrict__ diff, const float* __restrict__ dist,
                       const float* __restrict__ dirn,
                       const float* __restrict__ WC, const float* __restrict__ bC,
                       int Ee) {
    extern __shared__ unsigned smu[];
    unsigned* wsT = smu;             // [128][WS]
    unsigned* es  = smu + 128 * WS;  // [128][ES] (tf32 A tile, later reused for Ce fp32)
    __shared__ float s_sum[128], s_sq[128];

    int tid = threadIdx.x;
    if (tid < 128) { s_sum[tid] = 0.f; s_sq[tid] = 0.f; }

    for (int idx = tid; idx < 128 * 128; idx += 256) {
        int n = idx >> 7, k = idx & 127;
        wsT[k * WS + n] = f2tf(WC[idx]);
    }
    int row0 = blockIdx.x * 128;
    for (int idx = tid; idx < 128 * 32; idx += 256) {
        int r = idx >> 5, c4 = (idx & 31) * 4;
        float4 v = (row0 + r < Ee) ? *(const float4*)(e + (size_t)(row0 + r) * Dm + c4)
                                   : make_float4(0.f, 0.f, 0.f, 0.f);
        uint4 u = { f2tf(v.x), f2tf(v.y), f2tf(v.z), f2tf(v.w) };
        *(uint4*)(es + r * ES + c4) = u;
    }
    __syncthreads();

    int wa = tid >> 5, lane = tid & 31;
    int wm = wa >> 1, wn = wa & 1;
    int q = lane >> 2, a = lane & 3;

    float acc[2][8][4];
#pragma unroll
    for (int mf = 0; mf < 2; mf++)
#pragma unroll
        for (int nf = 0; nf < 8; nf++)
#pragma unroll
            for (int i = 0; i < 4; i++) acc[mf][nf][i] = 0.f;

#pragma unroll
    for (int k0 = 0; k0 < 128; k0 += 8) {
        unsigned A[2][4];
#pragma unroll
        for (int mf = 0; mf < 2; mf++) {
            int r = wm * 32 + mf * 16 + q;
            A[mf][0] = es[r * ES + k0 + a];
            A[mf][1] = es[(r + 8) * ES + k0 + a];
            A[mf][2] = es[r * ES + k0 + a + 4];
            A[mf][3] = es[(r + 8) * ES + k0 + a + 4];
        }
        unsigned B[8][2];
#pragma unroll
        for (int nf = 0; nf < 8; nf++) {
            int n = wn * 64 + nf * 8 + q;
            B[nf][0] = wsT[(k0 + a) * WS + n];
            B[nf][1] = wsT[(k0 + a + 4) * WS + n];
        }
#pragma unroll
        for (int mf = 0; mf < 2; mf++)
#pragma unroll
            for (int nf = 0; nf < 8; nf++)
                mma_tf32(acc[mf][nf], A[mf][0], A[mf][1], A[mf][2], A[mf][3],
                         B[nf][0], B[nf][1]);
    }

    // restage Ce (+bias) to smem so epilogue gets contiguous rows
    __syncthreads();
    float* cef = (float*)es;
#pragma unroll
    for (int mf = 0; mf < 2; mf++)
#pragma unroll
        for (int nf = 0; nf < 8; nf++) {
            int col = wn * 64 + nf * 8 + 2 * a;
            float b0 = bC[col], b1 = bC[col + 1];
            int r0 = wm * 32 + mf * 16 + q;
            float2 v0 = { acc[mf][nf][0] + b0, acc[mf][nf][1] + b1 };
            *(float2*)&cef[r0 * ES + col] = v0;
            float2 v1 = { acc[mf][nf][2] + b0, acc[mf][nf][3] + b1 };
            *(float2*)&cef[(r0 + 8) * ES + col] = v1;
        }
    __syncthreads();

    // epilogue: warp wa handles rows [wa*16, wa*16+16); lane owns cols 4*lane..+3
    float psum[4] = {0.f, 0.f, 0.f, 0.f};
    float psq[4]  = {0.f, 0.f, 0.f, 0.f};
    int c0 = 4 * lane;

#pragma unroll 1
    for (int j = 0; j < 16; j++) {
        int ml = wa * 16 + j;
        int m = row0 + ml;
        if (m < Ee) {
            int s = src[m], t = dst[m];
            float4 ce  = *(float4*)&cef[ml * ES + c0];
            float4 dh  = *(const float4*)(g_Dh + (size_t)t * Dm + c0);
            float4 ehv = *(const float4*)(g_Eh + (size_t)s * Dm + c0);
            float4 bhv = *(const float4*)(g_Bh + (size_t)s * Dm + c0);

            float de0 = dh.x - ehv.x, de1 = dh.y - ehv.y;
            float de2 = dh.z - ehv.z, de3 = dh.w - ehv.w;
            float en0 = de0 + ce.x, en1 = de1 + ce.y;
            float en2 = de2 + ce.z, en3 = de3 + ce.w;
            float hv0 = bhv.x + de0, hv1 = bhv.y + de1;
            float hv2 = bhv.z + de2, hv3 = bhv.w + de3;

            float4 env = { en0, en1, en2, en3 };
            *(float4*)(g_enew + (size_t)m * Dm + c0) = env;

            psum[0] += en0; psum[1] += en1; psum[2] += en2; psum[3] += en3;
            psq[0] += en0 * en0; psq[1] += en1 * en1;
            psq[2] += en2 * en2; psq[3] += en3 * en3;

            float nrm = en0 * en0 + en1 * en1 + en2 * en2 + en3 * en3;
#pragma unroll
            for (int o = 16; o > 0; o >>= 1)
                nrm += __shfl_xor_sync(0xffffffffu, nrm, o);
            float sigma = expf(-0.5f * sqrtf(nrm));

            float dd  = dist[m];
            float f0  = diff[2 * m], f1 = diff[2 * m + 1];
            float inv = (dd > 0.f) ? (1.f / dd) : 1.f;
            float ed0 = f0 * inv, ed1 = f1 * inv;
            float vs0 = dirn[2 * s], vs1 = dirn[2 * s + 1];
            float vd0 = dirn[2 * t], vd1 = dirn[2 * t + 1];
            float uv  = vs0 * vd0 + vs1 * vd1;
            float ehd = ed0 * vd0 + ed1 * vd1;
            float gate = (smask[m] == 1) ? (0.5f * (1.f - ehd) * uv * sigma) : sigma;

            red_add_v4(g_ssh + (size_t)t * Dm + c0,
                       hv0 * gate, hv1 * gate, hv2 * gate, hv3 * gate);
        }
    }

#pragma unroll
    for (int i = 0; i < 4; i++) {
        atomicAdd(&s_sum[c0 + i], psum[i]);
        atomicAdd(&s_sq[c0 + i],  psq[i]);
    }
    __syncthreads();
    if (tid < 128) {
        atomicAdd(&g_esum[tid], s_sum[tid]);
        atomicAdd(&g_esq[tid],  s_sq[tid]);
    }
}

// ---------------------------------------------------------------------------
// BN stats for h_out_pre = Ah + sum_sigma_h
// ---------------------------------------------------------------------------
__global__ void k_hstats(int Nn) {
    __shared__ float ss[2][128], sq[2][128];
    int c  = threadIdx.x & 127;
    int rg = threadIdx.x >> 7;
    int r0 = blockIdx.x * 64;
    float s = 0.f, q = 0.f;
    for (int r = r0 + rg; r < r0 + 64 && r < Nn; r += 2) {
        float x = g_Ah[r * Dm + c] + g_ssh[r * Dm + c];
        s += x; q += x * x;
    }
    ss[rg][c] = s; sq[rg][c] = q;
    __syncthreads();
    if (rg == 0) {
        atomicAdd(&g_hsum[c], ss[0][c] + ss[1][c]);
        atomicAdd(&g_hsq[c],  sq[0][c] + sq[1][c]);
    }
}

// ---------------------------------------------------------------------------
// h epilogue: h_out = h + relu(BN(Ah + ssh))   (float4)
// ---------------------------------------------------------------------------
__global__ void k_hout(const float* __restrict__ h,
                       const float* __restrict__ gamma, const float* __restrict__ beta,
                       float* __restrict__ out, int Nn) {
    int idx = blockIdx.x * blockDim.x + threadIdx.x;  // float4 index
    if (idx >= Nn * 32) return;
    int c4 = (idx & 31) * 4;
    float invN = 1.f / (float)Nn;
    float4 sm = *(float4*)&g_hsum[c4];
    float4 sq = *(float4*)&g_hsq[c4];
    float4 gm = *(const float4*)&gamma[c4];
    float4 bt = *(const float4*)&beta[c4];
    float4 A  = ((const float4*)g_Ah)[idx];
    float4 S  = ((const float4*)g_ssh)[idx];
    float4 H  = ((const float4*)h)[idx];
    float4 o;
    {
        float mu = sm.x * invN, var = fmaxf(sq.x * invN - mu * mu, 0.f);
        float y = gm.x * (A.x + S.x - mu) * rsqrtf(var + 1e-5f) + bt.x;
        o.x = H.x + fmaxf(y, 0.f);
    }
    {
        float mu = sm.y * invN, var = fmaxf(sq.y * invN - mu * mu, 0.f);
        float y = gm.y * (A.y + S.y - mu) * rsqrtf(var + 1e-5f) + bt.y;
        o.y = H.y + fmaxf(y, 0.f);
    }
    {
        float mu = sm.z * invN, var = fmaxf(sq.z * invN - mu * mu, 0.f);
        float y = gm.z * (A.z + S.z - mu) * rsqrtf(var + 1e-5f) + bt.z;
        o.z = H.z + fmaxf(y, 0.f);
    }
    {
        float mu = sm.w * invN, var = fmaxf(sq.w * invN - mu * mu, 0.f);
        float y = gm.w * (A.w + S.w - mu) * rsqrtf(var + 1e-5f) + bt.w;
        o.w = H.w + fmaxf(y, 0.f);
    }
    ((float4*)out)[idx] = o;
}

// ---------------------------------------------------------------------------
// e epilogue: e_out = e + relu(BN(e_new))   (float4)
// ---------------------------------------------------------------------------
__global__ void k_eout(const float* __restrict__ e,
                       const float* __restrict__ gamma, const float* __restrict__ beta,
                       float* __restrict__ out, int Ee) {
    int idx = blockIdx.x * blockDim.x + threadIdx.x;  // float4 index
    if (idx >= Ee * 32) return;
    int c4 = (idx & 31) * 4;
    float invE = 1.f / (float)Ee;
    float4 sm = *(float4*)&g_esum[c4];
    float4 sq = *(float4*)&g_esq[c4];
    float4 gm = *(const float4*)&gamma[c4];
    float4 bt = *(const float4*)&beta[c4];
    float4 X  = ((const float4*)g_enew)[idx];
    float4 Ev = ((const float4*)e)[idx];
    float4 o;
    {
        float mu = sm.x * invE, var = fmaxf(sq.x * invE - mu * mu, 0.f);
        float y = gm.x * (X.x - mu) * rsqrtf(var + 1e-5f) + bt.x;
        o.x = Ev.x + fmaxf(y, 0.f);
    }
    {
        float mu = sm.y * invE, var = fmaxf(sq.y * invE - mu * mu, 0.f);
        float y = gm.y * (X.y - mu) * rsqrtf(var + 1e-5f) + bt.y;
        o.y = Ev.y + fmaxf(y, 0.f);
    }
    {
        float mu = sm.z * invE, var = fmaxf(sq.z * invE - mu * mu, 0.f);
        float y = gm.z * (X.z - mu) * rsqrtf(var + 1e-5f) + bt.z;
        o.z = Ev.z + fmaxf(y, 0.f);
    }
    {
        float mu = sm.w * invE, var = fmaxf(sq.w * invE - mu * mu, 0.f);
        float y = gm.w * (X.w - mu) * rsqrtf(var + 1e-5f) + bt.w;
        o.w = Ev.w + fmaxf(y, 0.f);
    }
    ((float4*)out)[idx] = o;
}

// ---------------------------------------------------------------------------
extern "C" void kernel_launch(void* const* d_in, const int* in_sizes, int n_in,
                              void* d_out, int out_size) {
    const float* h     = (const float*)d_in[0];
    const float* e     = (const float*)d_in[1];
    const int*   src   = (const int*)d_in[2];
    const int*   dst   = (const int*)d_in[3];
    const int*   smask = (const int*)d_in[4];
    const float* diff  = (const float*)d_in[5];
    const float* dist  = (const float*)d_in[6];
    const float* dirn  = (const float*)d_in[7];
    const float* WA = (const float*)d_in[8],  *bA = (const float*)d_in[9];
    const float* WB = (const float*)d_in[10], *bB = (const float*)d_in[11];
    const float* WC = (const float*)d_in[12], *bC = (const float*)d_in[13];
    const float* WD = (const float*)d_in[14], *bD = (const float*)d_in[15];
    const float* WE = (const float*)d_in[16], *bE = (const float*)d_in[17];
    const float* gh = (const float*)d_in[18], *bh = (const float*)d_in[19];
    const float* ge = (const float*)d_in[20], *be = (const float*)d_in[21];
    float* out = (float*)d_out;

    int Nn = in_sizes[0] / Dm;
    int Ee = in_sizes[2];

    cudaFuncSetAttribute(k_node_gemm, cudaFuncAttributeMaxDynamicSharedMemorySize, SMEM_GEMM);
    cudaFuncSetAttribute(k_edge,      cudaFuncAttributeMaxDynamicSharedMemorySize, SMEM_GEMM);

    k_zero<<<512, 256>>>();

    dim3 g1((Nn + 127) / 128, 4);
    k_node_gemm<<<g1, 256, SMEM_GEMM>>>(h, Nn, WA, bA, WB, bB, WD, bD, WE, bE);

    k_edge<<<(Ee + 127) / 128, 256, SMEM_GEMM>>>(e, src, dst, smask, diff, dist, dirn, WC, bC, Ee);

    k_hstats<<<(Nn + 63) / 64, 256>>>(Nn);

    k_hout<<<(Nn * 32 + 255) / 256, 256>>>(h, gh, bh, out, Nn);

    k_eout<<<(Ee * 32 + 255) / 256, 256>>>(e, ge, be, out + (size_t)Nn * Dm, Ee);
}